// round 14
// baseline (speedup 1.0000x reference)
#include <cuda_runtime.h>
#include <cstdint>
#include <cstddef>

#define TT 1024
#define BB 256
#define HH 512
#define OO 64
#define NBLK 128
#define NTHR 512

__device__ float g_hbuf[2][HH * BB];      // rotating h slots [k][b], tf32-rounded
__device__ float g_xT[TT * OO * BB];      // [t][o][b], tf32-rounded
__device__ unsigned g_flags[4][32][32];   // per-block release flags, 128B stride

__device__ __forceinline__ float tf32r(float x) {
    uint32_t u;
    asm("cvt.rna.tf32.f32 %0, %1;" : "=r"(u) : "f"(x));
    return __uint_as_float(u);
}

__device__ __forceinline__ void mma8(float* d, const float4 a4, float b0, float b1) {
    uint32_t A0 = __float_as_uint(a4.x), A1 = __float_as_uint(a4.y);
    uint32_t A2 = __float_as_uint(a4.z), A3 = __float_as_uint(a4.w);
    uint32_t B0 = __float_as_uint(b0), B1 = __float_as_uint(b1);
    asm volatile(
        "mma.sync.aligned.m16n8k8.row.col.f32.tf32.tf32.f32 "
        "{%0,%1,%2,%3}, {%4,%5,%6,%7}, {%8,%9}, {%0,%1,%2,%3};\n"
        : "+f"(d[0]), "+f"(d[1]), "+f"(d[2]), "+f"(d[3])
        : "r"(A0), "r"(A1), "r"(A2), "r"(A3), "r"(B0), "r"(B1));
}

__device__ __forceinline__ void cpa16(uint32_t dst, const void* src) {
    asm volatile("cp.async.ca.shared.global [%0], [%1], 16;\n" :: "r"(dst), "l"(src));
}

// fast sigmoid / tanh via MUFU EX2+RCP (rel err ~1e-7)
__device__ __forceinline__ float fsigmoid(float x) {
    return __fdividef(1.f, 1.f + __expf(-x));
}
__device__ __forceinline__ float ftanh(float x) {
    return 1.f - __fdividef(2.f, __expf(2.f * x) + 1.f);
}

// warp-0 collective: wait until the 8 producer flags of `slab` reach lvl.
// lanes 0-7 each watch one flag; whole warp ballots.
__device__ __forceinline__ void poll8(int bg, int slab, unsigned lvl, int lane) {
    const unsigned* fp = &g_flags[bg][slab * 8 + (lane & 7)][0];
    unsigned v;
    do {
        asm volatile("ld.acquire.gpu.u32 %0, [%1];" : "=r"(v) : "l"(fp) : "memory");
    } while (__ballot_sync(0xffffffffu, (lane >= 8) | (v >= lvl)) != 0xffffffffu);
}

__global__ void prep_h0(const float* __restrict__ code_vec) {
    if (blockIdx.x == 0)
        for (int i = threadIdx.x; i < 4096; i += 256) ((unsigned*)g_flags)[i] = 0u;
    int idx = blockIdx.x * 256 + threadIdx.x;
    if (idx < HH * BB) {
        int k = idx >> 8, b = idx & 255;
        g_hbuf[0][k * BB + b] = tf32r(code_vec[b * HH + k]);
    }
}

__global__ void prep_x(const float* __restrict__ target) {
    int t = blockIdx.x;
    for (int i = threadIdx.x; i < OO * BB; i += 256) {
        int o = i >> 8, b = i & 255;
        float v = (t == 0) ? 0.f : target[((size_t)(t - 1) * BB + b) * OO + o];
        g_xT[(size_t)t * OO * BB + i] = tf32r(v);
    }
}

__global__ void dummy_k(int x) { if (x == 12345 && threadIdx.x > 1024) g_flags[0][0][0] = 1; }

// SMEM floats: Wp 27648 | buf 2x[128][72]=18432 (xch 16384 overlays)
//            | sx [64][72]=4608 | woP [72][32]float2=4608 | yx 512
#define SM_BUF 27648
#define SM_SX  46080
#define SM_WOP 50688
#define SM_YX  55296
#define SM_TOTF 55808   // 223232 B

__global__ __launch_bounds__(NTHR, 1) void gru_persistent(
    float* __restrict__ out, const float* __restrict__ code_vec,
    const float* __restrict__ w_ih, const float* __restrict__ w_hh,
    const float* __restrict__ b_ih, const float* __restrict__ b_hh,
    const float* __restrict__ w_out, const float* __restrict__ b_out) {
    extern __shared__ float sm[];
    float4* Wp4 = reinterpret_cast<float4*>(sm);
    float* buf = sm + SM_BUF;
    float* sx = sm + SM_SX;
    float2* woP = reinterpret_cast<float2*>(sm + SM_WOP);
    float* yx = sm + SM_YX;
    float* xch = buf;

    const int tid = threadIdx.x;
    const int mg = blockIdx.x & 31;
    const int bg = blockIdx.x >> 5;
    const int hid0 = mg * 16;
    const int b0 = bg * 64;
    const int lane = tid & 31, w = tid >> 5;
    const int ks = w >> 2, nq = w & 3;      // 4 K-slices x 4 n-quarters
    const int qr = lane >> 2, qc = lane & 3;
    const int n0 = nq * 16;
    const int orow0 = mg * 2;
    const int o0 = mg & 3;                  // rotated first slab
    const int wb_w = nq >> 1, hi_w = nq & 1;
    const int wXbase = (ks * 2 + wb_w) * 2048 + qr * 32;
    const int wbank0 = 4 * qr + qc + 16 * hi_w;

    const uint32_t smem_b = (uint32_t)__cvta_generic_to_shared(sm);
    const uint32_t buf_b = smem_b + SM_BUF * 4u;

    // pack gate weights into A-fragment layout (validated R1/R3/R5-R13)
    for (int idx = tid; idx < 72 * 96; idx += NTHR) {
        int kstep = idx / 96, r = idx % 96;
        int g = r >> 5, ln = r & 31;
        int lqr = ln >> 2, lqc = ln & 3;
        int row0 = g * HH + hid0 + lqr;
        int c0 = kstep * 8 + lqc, c1 = c0 + 4;
        float4 v;
        v.x = tf32r(c0 < HH ? w_hh[(size_t)row0 * HH + c0] : w_ih[(size_t)row0 * OO + c0 - HH]);
        v.y = tf32r(c0 < HH ? w_hh[(size_t)(row0 + 8) * HH + c0] : w_ih[(size_t)(row0 + 8) * OO + c0 - HH]);
        v.z = tf32r(c1 < HH ? w_hh[(size_t)row0 * HH + c1] : w_ih[(size_t)row0 * OO + c1 - HH]);
        v.w = tf32r(c1 < HH ? w_hh[(size_t)(row0 + 8) * HH + c1] : w_ih[(size_t)(row0 + 8) * OO + c1 - HH]);
        Wp4[idx] = v;
    }
    // pack y A-fragments: rows {w_out[orow0], w_out[orow0+1], 0...}, h-ksteps only
    for (int idx = tid; idx < 72 * 32; idx += NTHR) {
        int kstep = idx >> 5, ln = idx & 31;
        int lqr = ln >> 2, lqc = ln & 3;
        float2 v = make_float2(0.f, 0.f);
        if (kstep < 64 && lqr < 2) {
            int c0 = kstep * 8 + lqc;
            v.x = tf32r(w_out[(size_t)(orow0 + lqr) * HH + c0]);
            v.y = tf32r(w_out[(size_t)(orow0 + lqr) * HH + c0 + 4]);
        }
        woP[idx] = v;
    }

    const int krb = tid >> 6, bcol = tid & 63;
    float brv[2], bzv[2], binv[2], bhnv[2];
    #pragma unroll
    for (int r2 = 0; r2 < 2; ++r2) {
        int u = hid0 + krb + 8 * r2;
        brv[r2] = b_ih[u] + b_hh[u];
        bzv[r2] = b_ih[HH + u] + b_hh[HH + u];
        binv[r2] = b_ih[2 * HH + u];
        bhnv[r2] = b_hh[2 * HH + u];
    }
    const int hir = (bcol >> 4) & 1, wbr = bcol >> 5, jr = (bcol >> 3) & 1;
    const int qcr = (bcol & 7) >> 1, er = bcol & 1;
    const int rbank = (4 * krb + qcr + 8 * jr + 4 * er + 16 * hir) & 31;
    const int rbase = wbr * 2048 + krb * 32 + rbank;
    const float yb = (tid < 128) ? b_out[orow0 + (tid >> 6)] : 0.f;
    const int ynq = bcol >> 4, ylo = bcol & 15;

    // h_prev carried raw fp32 in registers (full-precision z*h path)
    float hprev[2];
    #pragma unroll
    for (int r2 = 0; r2 < 2; ++r2)
        hprev[r2] = code_vec[(size_t)(b0 + bcol) * HH + hid0 + krb + 8 * r2];

    // stage x[0]; prefetch x[1] into registers
    float4 xr[2];
    #pragma unroll
    for (int j = 0; j < 2; ++j) {
        int idx = j * NTHR + tid;
        int row = idx >> 4, c4 = (idx & 15) << 2;
        *reinterpret_cast<float4*>(&sx[row * 72 + c4]) =
            *reinterpret_cast<const float4*>(g_xT + (size_t)row * BB + b0 + c4);
        xr[j] = *reinterpret_cast<const float4*>(g_xT + (size_t)OO * BB + (size_t)row * BB + b0 + c4);
    }

    for (int t = 0; t < TT; ++t) {
        const float* hsrc = g_hbuf[t & 1];
        const unsigned lvl = (unsigned)t;

        // T0: wait only for THIS block's first slab producers (wavefront start)
        if (w == 0) poll8(bg, o0, lvl, lane);
        __syncthreads();   // publishes poll + sx tail staging + xch reads done

        float acc[3][2][4] = {}, accX[2][4] = {}, accY[2][4] = {};

        // first (rotated) slab via cp.async
        {
            const float* src = hsrc + (size_t)(128 * o0) * BB + b0;
            #pragma unroll
            for (int j = 0; j < 4; ++j) {
                int idx = j * NTHR + tid;
                int row = idx >> 4, c4 = (idx & 15) << 2;
                cpa16(buf_b + (uint32_t)((row * 72 + c4) * 4), src + (size_t)row * BB + c4);
            }
        }
        asm volatile("cp.async.commit_group;\n");

        // x-path compute (covers first slab's L2 latency)
        #pragma unroll
        for (int c2 = 0; c2 < 2; ++c2) {
            const int gk = 64 + ks * 2 + c2;
            const int kk = (ks * 2 + c2) * 8;
            float bf0[2], bf1[2];
            #pragma unroll
            for (int j = 0; j < 2; ++j) {
                bf0[j] = sx[(kk + qc) * 72 + n0 + j * 8 + qr];
                bf1[j] = sx[(kk + 4 + qc) * 72 + n0 + j * 8 + qr];
            }
            float4 a0 = Wp4[(gk * 3 + 0) * 32 + lane];
            float4 a1 = Wp4[(gk * 3 + 1) * 32 + lane];
            float4 a2 = Wp4[(gk * 3 + 2) * 32 + lane];
            #pragma unroll
            for (int j = 0; j < 2; ++j) {
                mma8(acc[0][j], a0, bf0[j], bf1[j]);
                mma8(acc[1][j], a1, bf0[j], bf1[j]);
                mma8(accX[j], a2, bf0[j], bf1[j]);
            }
        }

        #pragma unroll
        for (int i = 0; i < 4; ++i) {
            // warp 0 gates the NEXT slab's producers before anyone stages it
            if (i < 3 && w == 0) poll8(bg, (o0 + i + 1) & 3, lvl, lane);
            asm volatile("cp.async.wait_group 0;\n");
            __syncthreads();   // slab i ready AND poll passed
            if (i < 3) {
                const int pn = (o0 + i + 1) & 3;
                const float* src = hsrc + (size_t)(128 * pn) * BB + b0;
                uint32_t dstb = buf_b + (uint32_t)(((i + 1) & 1) * 9216 * 4);
                #pragma unroll
                for (int j = 0; j < 4; ++j) {
                    int idx = j * NTHR + tid;
                    int row = idx >> 4, c4 = (idx & 15) << 2;
                    cpa16(dstb + (uint32_t)((row * 72 + c4) * 4), src + (size_t)row * BB + c4);
                }
                asm volatile("cp.async.commit_group;\n");
            }
            const int p = (o0 + i) & 3;
            const float* bs = buf + (i & 1) * 9216;
            #pragma unroll
            for (int c = 0; c < 4; ++c) {
                const int gk = p * 16 + ks * 4 + c;
                const int kk = (ks * 4 + c) * 8;
                float bf0[2], bf1[2];
                #pragma unroll
                for (int j = 0; j < 2; ++j) {
                    bf0[j] = bs[(kk + qc) * 72 + n0 + j * 8 + qr];      // pre-rounded
                    bf1[j] = bs[(kk + 4 + qc) * 72 + n0 + j * 8 + qr];
                }
                #pragma unroll
                for (int g = 0; g < 3; ++g) {
                    float4 a4 = Wp4[(gk * 3 + g) * 32 + lane];
                    mma8(acc[g][0], a4, bf0[0], bf1[0]);
                    mma8(acc[g][1], a4, bf0[1], bf1[1]);
                }
                float2 ay2 = woP[gk * 32 + lane];
                float4 ay = make_float4(ay2.x, 0.f, ay2.y, 0.f);
                mma8(accY[0], ay, bf0[0], bf1[0]);
                mma8(accY[1], ay, bf0[1], bf1[1]);
            }
        }

        __syncthreads();  // S1: done reading buf/sx; overlay exchange
        #pragma unroll
        for (int g = 0; g < 4; ++g)
            #pragma unroll
            for (int rh = 0; rh < 2; ++rh)
                #pragma unroll
                for (int j = 0; j < 2; ++j)
                    #pragma unroll
                    for (int el = 0; el < 2; ++el) {
                        float v = (g < 3) ? acc[g][j][rh * 2 + el] : accX[j][rh * 2 + el];
                        xch[wXbase + g * 512 + rh * 256 + ((wbank0 + 8 * j + 4 * el) & 31)] = v;
                    }
        if (qr < 2) {
            #pragma unroll
            for (int j = 0; j < 2; ++j) {
                yx[(w * 2 + qr) * 16 + j * 8 + qc * 2] = accY[j][0];
                yx[(w * 2 + qr) * 16 + j * 8 + qc * 2 + 1] = accY[j][1];
            }
        }
        __syncthreads();  // S2

        // GRU update + h store (fast-math epilogue)
        float* hdst = g_hbuf[(t + 1) & 1];
        #pragma unroll
        for (int r2 = 0; r2 < 2; ++r2) {
            float q0 = 0.f, q1 = 0.f, q2s = 0.f, q3 = 0.f;
            #pragma unroll
            for (int ksx = 0; ksx < 4; ++ksx) {
                const float* sl = xch + rbase + ksx * 4096 + r2 * 256;
                q0 += sl[0]; q1 += sl[512]; q2s += sl[1024]; q3 += sl[1536];
            }
            float r = fsigmoid(q0 + brv[r2]);
            float z = fsigmoid(q1 + bzv[r2]);
            float n = ftanh(q3 + binv[r2] + r * (q2s + bhnv[r2]));
            float hv = (1.f - z) * n + z * hprev[r2];
            hprev[r2] = hv;
            hdst[(size_t)(hid0 + krb + 8 * r2) * BB + b0 + bcol] = tf32r(hv);
            if (t == TT - 1)
                out[(size_t)TT * BB * OO + (size_t)(b0 + bcol) * HH + hid0 + krb + 8 * r2] = hv;
        }
        __syncthreads();   // S3: all h stores done

        // release own flag (ordered after h stores by release semantics)
        if (tid == 0)
            asm volatile("st.release.gpu.u32 [%0], %1;"
                         :: "l"(&g_flags[bg][mg][0]), "r"((unsigned)(t + 1)) : "memory");
        // y stores + x staging overlap the flag propagation
        if (t > 0 && tid < 128) {
            int o2 = tid >> 6, b = tid & 63;
            float y = yb;
            #pragma unroll
            for (int ksx = 0; ksx < 4; ++ksx)
                y += yx[((ksx * 4 + ynq) * 2 + o2) * 16 + ylo];
            out[((size_t)(t - 1) * BB + b0 + b) * OO + orow0 + o2] = y;
        }
        if (t + 1 < TT) {
            #pragma unroll
            for (int j = 0; j < 2; ++j) {
                int idx = j * NTHR + tid;
                int row = idx >> 4, c4 = (idx & 15) << 2;
                *reinterpret_cast<float4*>(&sx[row * 72 + c4]) = xr[j];
            }
            if (t + 2 < TT) {
                const float* xn = g_xT + (size_t)(t + 2) * OO * BB;
                #pragma unroll
                for (int j = 0; j < 2; ++j) {
                    int idx = j * NTHR + tid;
                    int row = idx >> 4, c4 = (idx & 15) << 2;
                    xr[j] = *reinterpret_cast<const float4*>(xn + (size_t)row * BB + b0 + c4);
                }
            }
        }
        // no end-of-step rendezvous — next step's per-slab polls gate everything
    }

    // final y[1023] from h[1024]: need all 32 producers at level TT
    {
        if (w == 0) {
            const unsigned* fp = &g_flags[bg][lane][0];
            unsigned v;
            do {
                asm volatile("ld.acquire.gpu.u32 %0, [%1];" : "=r"(v) : "l"(fp) : "memory");
            } while (__ballot_sync(0xffffffffu, v >= (unsigned)TT) != 0xffffffffu);
        }
        __syncthreads();
        const float* hsrc = g_hbuf[TT & 1];
        int o2 = (tid >> 6) & 1, q = tid >> 7;
        const int kbeg = q * 128;
        float yp = 0.f;
        for (int k = kbeg; k < kbeg + 128; ++k)
            yp = fmaf(hsrc[(size_t)k * BB + b0 + bcol], w_out[(size_t)(orow0 + o2) * HH + k], yp);
        __syncthreads();
        yx[(q * 2 + o2) * 64 + bcol] = yp;
        __syncthreads();
        if (tid < 128) {
            int oo2 = tid >> 6, b = tid & 63;
            float y = yx[oo2 * 64 + b] + yx[(2 + oo2) * 64 + b] +
                      yx[(4 + oo2) * 64 + b] + yx[(6 + oo2) * 64 + b] + yb;
            out[((size_t)(TT - 1) * BB + b0 + b) * OO + orow0 + oo2] = y;
        }
    }
}

extern "C" void kernel_launch(void* const* d_in, const int* in_sizes, int n_in,
                              void* d_out, int out_size) {
    const float* code_vec = (const float*)d_in[0];
    const float* target   = (const float*)d_in[1];
    const float* w_ih     = (const float*)d_in[2];
    const float* w_hh     = (const float*)d_in[3];
    const float* b_ih     = (const float*)d_in[4];
    const float* b_hh     = (const float*)d_in[5];
    const float* w_out    = (const float*)d_in[6];
    const float* b_out    = (const float*)d_in[7];
    float* out = (float*)d_out;

    const size_t smem_step = SM_TOTF * sizeof(float);   // 223232 B
    cudaFuncSetAttribute(gru_persistent, cudaFuncAttributeMaxDynamicSharedMemorySize, (int)smem_step);

    prep_h0<<<(HH * BB + 255) / 256, 256>>>(code_vec);       // idx 0
    prep_x<<<TT, 256>>>(target);                             // idx 1
    dummy_k<<<1, 32>>>(0);                                   // idx 2
    gru_persistent<<<NBLK, NTHR, smem_step>>>(out, code_vec, w_ih, w_hh, b_ih, b_hh, w_out, b_out);  // idx 3 <- ncu
}

// round 15
// speedup vs baseline: 1.0306x; 1.0306x over previous
#include <cuda_runtime.h>
#include <cstdint>
#include <cstddef>

#define TT 1024
#define BB 256
#define HH 512
#define OO 64
#define NBLK 128
#define NTHR 512

__device__ float g_hbuf[2][HH * BB];    // rotating h slots [k][b], tf32-rounded
__device__ float g_xT[TT * OO * BB];    // [t][o][b], tf32-rounded
__device__ unsigned g_cnt4[4];          // per-batch-group barrier counters

__device__ __forceinline__ float tf32r(float x) {
    uint32_t u;
    asm("cvt.rna.tf32.f32 %0, %1;" : "=r"(u) : "f"(x));
    return __uint_as_float(u);
}

__device__ __forceinline__ void mma8(float* d, const float4 a4, float b0, float b1) {
    uint32_t A0 = __float_as_uint(a4.x), A1 = __float_as_uint(a4.y);
    uint32_t A2 = __float_as_uint(a4.z), A3 = __float_as_uint(a4.w);
    uint32_t B0 = __float_as_uint(b0), B1 = __float_as_uint(b1);
    asm volatile(
        "mma.sync.aligned.m16n8k8.row.col.f32.tf32.tf32.f32 "
        "{%0,%1,%2,%3}, {%4,%5,%6,%7}, {%8,%9}, {%0,%1,%2,%3};\n"
        : "+f"(d[0]), "+f"(d[1]), "+f"(d[2]), "+f"(d[3])
        : "r"(A0), "r"(A1), "r"(A2), "r"(A3), "r"(B0), "r"(B1));
}

// fast sigmoid / tanh via MUFU EX2+RCP (rel err ~1e-7)
__device__ __forceinline__ float fsigmoid(float x) {
    return __fdividef(1.f, 1.f + __expf(-x));
}
__device__ __forceinline__ float ftanh(float x) {
    return 1.f - __fdividef(2.f, __expf(2.f * x) + 1.f);
}

__global__ void prep_h0(const float* __restrict__ code_vec) {
    if (blockIdx.x == 0 && threadIdx.x < 4) g_cnt4[threadIdx.x] = 0u;
    int idx = blockIdx.x * 256 + threadIdx.x;
    if (idx < HH * BB) {
        int k = idx >> 8, b = idx & 255;
        g_hbuf[0][k * BB + b] = tf32r(code_vec[b * HH + k]);
    }
}

__global__ void prep_x(const float* __restrict__ target) {
    int t = blockIdx.x;
    for (int i = threadIdx.x; i < OO * BB; i += 256) {
        int o = i >> 8, b = i & 255;
        float v = (t == 0) ? 0.f : target[((size_t)(t - 1) * BB + b) * OO + o];
        g_xT[(size_t)t * OO * BB + i] = tf32r(v);
    }
}

__global__ void dummy_k(int x) { if (x == 12345 && threadIdx.x > 1024) g_cnt4[0] = 1; }

// SMEM floats: Wp 27648 | xch 16384 | woP [72][32]float2 = 4608 | yx 512
#define SM_XCH 27648
#define SM_WOP (27648 + 16384)
#define SM_YX  (27648 + 16384 + 4608)
#define SM_TOTF (27648 + 16384 + 4608 + 512)   // 49152 f = 196608 B

__global__ __launch_bounds__(NTHR, 1) void gru_persistent(
    float* __restrict__ out, const float* __restrict__ code_vec,
    const float* __restrict__ w_ih, const float* __restrict__ w_hh,
    const float* __restrict__ b_ih, const float* __restrict__ b_hh,
    const float* __restrict__ w_out, const float* __restrict__ b_out) {
    extern __shared__ float sm[];
    float4* Wp4 = reinterpret_cast<float4*>(sm);
    float* xch = sm + SM_XCH;
    float2* woP = reinterpret_cast<float2*>(sm + SM_WOP);
    float* yx = sm + SM_YX;

    const int tid = threadIdx.x;
    const int mg = blockIdx.x & 31;
    const int bg = blockIdx.x >> 5;
    const int hid0 = mg * 16;
    const int b0 = bg * 64;
    const int lane = tid & 31, w = tid >> 5;
    const int ks = w >> 2, nq = w & 3;      // 4 K-slices x 4 n-quarters
    const int qr = lane >> 2, qc = lane & 3;
    const int n0 = nq * 16;
    const int orow0 = mg * 2;
    const int o0 = mg & 3;                  // rotated first slab
    const int wb_w = nq >> 1, hi_w = nq & 1;
    const int wXbase = (ks * 2 + wb_w) * 2048 + qr * 32;
    const int wbank0 = 4 * qr + qc + 16 * hi_w;

    // pack gate weights into A-fragment layout (validated R1/R3/R5-R14)
    for (int idx = tid; idx < 72 * 96; idx += NTHR) {
        int kstep = idx / 96, r = idx % 96;
        int g = r >> 5, ln = r & 31;
        int lqr = ln >> 2, lqc = ln & 3;
        int row0 = g * HH + hid0 + lqr;
        int c0 = kstep * 8 + lqc, c1 = c0 + 4;
        float4 v;
        v.x = tf32r(c0 < HH ? w_hh[(size_t)row0 * HH + c0] : w_ih[(size_t)row0 * OO + c0 - HH]);
        v.y = tf32r(c0 < HH ? w_hh[(size_t)(row0 + 8) * HH + c0] : w_ih[(size_t)(row0 + 8) * OO + c0 - HH]);
        v.z = tf32r(c1 < HH ? w_hh[(size_t)row0 * HH + c1] : w_ih[(size_t)row0 * OO + c1 - HH]);
        v.w = tf32r(c1 < HH ? w_hh[(size_t)(row0 + 8) * HH + c1] : w_ih[(size_t)(row0 + 8) * OO + c1 - HH]);
        Wp4[idx] = v;
    }
    // pack y A-fragments: rows {w_out[orow0], w_out[orow0+1], 0...}, h-ksteps only
    for (int idx = tid; idx < 72 * 32; idx += NTHR) {
        int kstep = idx >> 5, ln = idx & 31;
        int lqr = ln >> 2, lqc = ln & 3;
        float2 v = make_float2(0.f, 0.f);
        if (kstep < 64 && lqr < 2) {
            int c0 = kstep * 8 + lqc;
            v.x = tf32r(w_out[(size_t)(orow0 + lqr) * HH + c0]);
            v.y = tf32r(w_out[(size_t)(orow0 + lqr) * HH + c0 + 4]);
        }
        woP[idx] = v;
    }

    const int krb = tid >> 6, bcol = tid & 63;
    float brv[2], bzv[2], binv[2], bhnv[2];
    #pragma unroll
    for (int r2 = 0; r2 < 2; ++r2) {
        int u = hid0 + krb + 8 * r2;
        brv[r2] = b_ih[u] + b_hh[u];
        bzv[r2] = b_ih[HH + u] + b_hh[HH + u];
        binv[r2] = b_ih[2 * HH + u];
        bhnv[r2] = b_hh[2 * HH + u];
    }
    const int hir = (bcol >> 4) & 1, wbr = bcol >> 5, jr = (bcol >> 3) & 1;
    const int qcr = (bcol & 7) >> 1, er = bcol & 1;
    const int rbank = (4 * krb + qcr + 8 * jr + 4 * er + 16 * hir) & 31;
    const int rbase = wbr * 2048 + krb * 32 + rbank;
    const float yb = (tid < 128) ? b_out[orow0 + (tid >> 6)] : 0.f;
    const int ynq = bcol >> 4, ylo = bcol & 15;

    // h_prev carried raw fp32 in registers (full-precision z*h path)
    float hprev[2];
    #pragma unroll
    for (int r2 = 0; r2 < 2; ++r2)
        hprev[r2] = code_vec[(size_t)(b0 + bcol) * HH + hid0 + krb + 8 * r2];

    // per-warp B LDG base offset (cols b0+n0+qr; rows via *BB)
    const int bcolBase = b0 + n0 + qr;

    __syncthreads();   // Wp/woP ready

    for (int t = 0; t < TT; ++t) {
        const float* hsrc = g_hbuf[t & 1];
        const float* xsrc = g_xT + (size_t)t * OO * BB;

        float acc[3][2][4] = {}, accX[2][4] = {}, accY[2][4] = {};
        float Bb[2][4][4];   // [slot][c][bf0j0,bf0j1,bf1j0,bf1j1]

        // load x fragments (2 ksteps) + first slab's B directly from L2
        float Bx[2][4];
        #pragma unroll
        for (int c2 = 0; c2 < 2; ++c2) {
            const float* r0 = xsrc + (size_t)((ks * 2 + c2) * 8 + qc) * BB + bcolBase;
            const float* r1 = r0 + 4 * BB;
            Bx[c2][0] = r0[0]; Bx[c2][1] = r0[8];
            Bx[c2][2] = r1[0]; Bx[c2][3] = r1[8];
        }
        #pragma unroll
        for (int c = 0; c < 4; ++c) {
            const float* r0 = hsrc + (size_t)(o0 * 128 + (ks * 4 + c) * 8 + qc) * BB + bcolBase;
            const float* r1 = r0 + 4 * BB;
            Bb[0][c][0] = r0[0]; Bb[0][c][1] = r0[8];
            Bb[0][c][2] = r1[0]; Bb[0][c][3] = r1[8];
        }

        // x-path MMAs (cover first slab's L2 latency)
        #pragma unroll
        for (int c2 = 0; c2 < 2; ++c2) {
            const int gk = 64 + ks * 2 + c2;
            float4 a0 = Wp4[(gk * 3 + 0) * 32 + lane];
            float4 a1 = Wp4[(gk * 3 + 1) * 32 + lane];
            float4 a2 = Wp4[(gk * 3 + 2) * 32 + lane];
            #pragma unroll
            for (int j = 0; j < 2; ++j) {
                mma8(acc[0][j], a0, Bx[c2][j], Bx[c2][2 + j]);
                mma8(acc[1][j], a1, Bx[c2][j], Bx[c2][2 + j]);
                mma8(accX[j], a2, Bx[c2][j], Bx[c2][2 + j]);
            }
        }

        // 4 slabs; B register double-buffer; NO block syncs in mainloop
        #pragma unroll
        for (int i = 0; i < 4; ++i) {
            if (i < 3) {
                const int pn = (o0 + i + 1) & 3;
                #pragma unroll
                for (int c = 0; c < 4; ++c) {
                    const float* r0 = hsrc + (size_t)(pn * 128 + (ks * 4 + c) * 8 + qc) * BB + bcolBase;
                    const float* r1 = r0 + 4 * BB;
                    Bb[(i + 1) & 1][c][0] = r0[0]; Bb[(i + 1) & 1][c][1] = r0[8];
                    Bb[(i + 1) & 1][c][2] = r1[0]; Bb[(i + 1) & 1][c][3] = r1[8];
                }
            }
            const int p = (o0 + i) & 3;
            const float(*B)[4] = Bb[i & 1];
            #pragma unroll
            for (int c = 0; c < 4; ++c) {
                const int gk = p * 16 + ks * 4 + c;
                #pragma unroll
                for (int g = 0; g < 3; ++g) {
                    float4 a4 = Wp4[(gk * 3 + g) * 32 + lane];
                    mma8(acc[g][0], a4, B[c][0], B[c][2]);
                    mma8(acc[g][1], a4, B[c][1], B[c][3]);
                }
                float2 ay2 = woP[gk * 32 + lane];
                float4 ay = make_float4(ay2.x, 0.f, ay2.y, 0.f);
                mma8(accY[0], ay, B[c][0], B[c][2]);
                mma8(accY[1], ay, B[c][1], B[c][3]);
            }
        }

        // exchange writes (xch reads of previous step completed before last S4)
        #pragma unroll
        for (int g = 0; g < 4; ++g)
            #pragma unroll
            for (int rh = 0; rh < 2; ++rh)
                #pragma unroll
                for (int j = 0; j < 2; ++j)
                    #pragma unroll
                    for (int el = 0; el < 2; ++el) {
                        float v = (g < 3) ? acc[g][j][rh * 2 + el] : accX[j][rh * 2 + el];
                        xch[wXbase + g * 512 + rh * 256 + ((wbank0 + 8 * j + 4 * el) & 31)] = v;
                    }
        if (qr < 2) {
            #pragma unroll
            for (int j = 0; j < 2; ++j) {
                yx[(w * 2 + qr) * 16 + j * 8 + qc * 2] = accY[j][0];
                yx[(w * 2 + qr) * 16 + j * 8 + qc * 2 + 1] = accY[j][1];
            }
        }
        __syncthreads();  // S2: exchange visible

        // GRU update + h store (fast-math epilogue)
        float* hdst = g_hbuf[(t + 1) & 1];
        #pragma unroll
        for (int r2 = 0; r2 < 2; ++r2) {
            float q0 = 0.f, q1 = 0.f, q2s = 0.f, q3 = 0.f;
            #pragma unroll
            for (int ksx = 0; ksx < 4; ++ksx) {
                const float* sl = xch + rbase + ksx * 4096 + r2 * 256;
                q0 += sl[0]; q1 += sl[512]; q2s += sl[1024]; q3 += sl[1536];
            }
            float r = fsigmoid(q0 + brv[r2]);
            float z = fsigmoid(q1 + bzv[r2]);
            float n = ftanh(q3 + binv[r2] + r * (q2s + bhnv[r2]));
            float hv = (1.f - z) * n + z * hprev[r2];
            hprev[r2] = hv;
            hdst[(size_t)(hid0 + krb + 8 * r2) * BB + b0 + bcol] = tf32r(hv);
            if (t == TT - 1)
                out[(size_t)TT * BB * OO + (size_t)(b0 + bcol) * HH + hid0 + krb + 8 * r2] = hv;
        }
        __syncthreads();   // S3: all h stores done

        // release, overlap poll with y stores (R12's winning barrier form)
        if (tid == 0)
            asm volatile("red.release.gpu.add.u32 [%0], %1;"
                         :: "l"(&g_cnt4[bg]), "r"(1u) : "memory");
        if (t > 0 && tid < 128) {
            int o2 = tid >> 6, b = tid & 63;
            float y = yb;
            #pragma unroll
            for (int ksx = 0; ksx < 4; ++ksx)
                y += yx[((ksx * 4 + ynq) * 2 + o2) * 16 + ylo];
            out[((size_t)(t - 1) * BB + b0 + b) * OO + orow0 + o2] = y;
        }
        if (tid == 0) {
            unsigned tgt = 32u * (unsigned)(t + 1), v;
            do {
                asm volatile("ld.acquire.gpu.u32 %0, [%1];" : "=r"(v) : "l"(&g_cnt4[bg]) : "memory");
            } while (v < tgt);
        }
        __syncthreads();  // S4: h[t+1] ready chip-wide
    }

    // final y[1023] from h[1024]
    {
        const float* hsrc = g_hbuf[TT & 1];
        int o2 = (tid >> 6) & 1, q = tid >> 7;
        const int kbeg = q * 128;
        float yp = 0.f;
        for (int k = kbeg; k < kbeg + 128; ++k)
            yp = fmaf(hsrc[(size_t)k * BB + b0 + bcol], w_out[(size_t)(orow0 + o2) * HH + k], yp);
        __syncthreads();
        yx[(q * 2 + o2) * 64 + bcol] = yp;
        __syncthreads();
        if (tid < 128) {
            int oo2 = tid >> 6, b = tid & 63;
            float y = yx[oo2 * 64 + b] + yx[(2 + oo2) * 64 + b] +
                      yx[(4 + oo2) * 64 + b] + yx[(6 + oo2) * 64 + b] + yb;
            out[((size_t)(TT - 1) * BB + b0 + b) * OO + orow0 + oo2] = y;
        }
    }
}

extern "C" void kernel_launch(void* const* d_in, const int* in_sizes, int n_in,
                              void* d_out, int out_size) {
    const float* code_vec = (const float*)d_in[0];
    const float* target   = (const float*)d_in[1];
    const float* w_ih     = (const float*)d_in[2];
    const float* w_hh     = (const float*)d_in[3];
    const float* b_ih     = (const float*)d_in[4];
    const float* b_hh     = (const float*)d_in[5];
    const float* w_out    = (const float*)d_in[6];
    const float* b_out    = (const float*)d_in[7];
    float* out = (float*)d_out;

    const size_t smem_step = SM_TOTF * sizeof(float);   // 196608 B
    cudaFuncSetAttribute(gru_persistent, cudaFuncAttributeMaxDynamicSharedMemorySize, (int)smem_step);

    prep_h0<<<(HH * BB + 255) / 256, 256>>>(code_vec);       // idx 0
    prep_x<<<TT, 256>>>(target);                             // idx 1
    dummy_k<<<1, 32>>>(0);                                   // idx 2
    gru_persistent<<<NBLK, NTHR, smem_step>>>(out, code_vec, w_ih, w_hh, b_ih, b_hh, w_out, b_out);  // idx 3 <- ncu
}

// round 16
// speedup vs baseline: 1.2067x; 1.1709x over previous
#include <cuda_runtime.h>
#include <cstdint>
#include <cstddef>

#define TT 1024
#define BB 256
#define HH 512
#define OO 64
#define NBLK 128
#define NTHR 512

__device__ float g_hbuf[2][HH * BB];    // rotating h slots [k][b], tf32-rounded
__device__ float g_xT[TT * OO * BB];    // [t][o][b], tf32-rounded
__device__ unsigned g_cnt4[4];          // per-batch-group barrier counters

__device__ __forceinline__ float tf32r(float x) {
    uint32_t u;
    asm("cvt.rna.tf32.f32 %0, %1;" : "=r"(u) : "f"(x));
    return __uint_as_float(u);
}

__device__ __forceinline__ void mma8(float* d, const float4 a4, float b0, float b1) {
    uint32_t A0 = __float_as_uint(a4.x), A1 = __float_as_uint(a4.y);
    uint32_t A2 = __float_as_uint(a4.z), A3 = __float_as_uint(a4.w);
    uint32_t B0 = __float_as_uint(b0), B1 = __float_as_uint(b1);
    asm volatile(
        "mma.sync.aligned.m16n8k8.row.col.f32.tf32.tf32.f32 "
        "{%0,%1,%2,%3}, {%4,%5,%6,%7}, {%8,%9}, {%0,%1,%2,%3};\n"
        : "+f"(d[0]), "+f"(d[1]), "+f"(d[2]), "+f"(d[3])
        : "r"(A0), "r"(A1), "r"(A2), "r"(A3), "r"(B0), "r"(B1));
}

__device__ __forceinline__ void cpa16(uint32_t dst, const void* src) {
    asm volatile("cp.async.cg.shared.global [%0], [%1], 16;\n" :: "r"(dst), "l"(src));
}

// fast sigmoid / tanh via MUFU EX2+RCP (rel err ~1e-7)
__device__ __forceinline__ float fsigmoid(float x) {
    return __fdividef(1.f, 1.f + __expf(-x));
}
__device__ __forceinline__ float ftanh(float x) {
    return 1.f - __fdividef(2.f, __expf(2.f * x) + 1.f);
}

__global__ void prep_h0(const float* __restrict__ code_vec) {
    if (blockIdx.x == 0 && threadIdx.x < 4) g_cnt4[threadIdx.x] = 0u;
    int idx = blockIdx.x * 256 + threadIdx.x;
    if (idx < HH * BB) {
        int k = idx >> 8, b = idx & 255;
        g_hbuf[0][k * BB + b] = tf32r(code_vec[b * HH + k]);
    }
}

__global__ void prep_x(const float* __restrict__ target) {
    int t = blockIdx.x;
    for (int i = threadIdx.x; i < OO * BB; i += 256) {
        int o = i >> 8, b = i & 255;
        float v = (t == 0) ? 0.f : target[((size_t)(t - 1) * BB + b) * OO + o];
        g_xT[(size_t)t * OO * BB + i] = tf32r(v);
    }
}

__global__ void dummy_k(int x) { if (x == 12345 && threadIdx.x > 1024) g_cnt4[0] = 1; }

// SMEM floats: Wp 27648 | buf 2x[128][72]=18432 (xch 16384 overlays)
//            | sx [64][72]=4608 | woP [72][32]float2=4608 | yx 512
#define SM_BUF 27648
#define SM_SX  46080
#define SM_WOP 50688
#define SM_YX  55296
#define SM_TOTF 55808   // 223232 B

__global__ __launch_bounds__(NTHR, 1) void gru_persistent(
    float* __restrict__ out, const float* __restrict__ code_vec,
    const float* __restrict__ w_ih, const float* __restrict__ w_hh,
    const float* __restrict__ b_ih, const float* __restrict__ b_hh,
    const float* __restrict__ w_out, const float* __restrict__ b_out) {
    extern __shared__ float sm[];
    float4* Wp4 = reinterpret_cast<float4*>(sm);
    float* buf = sm + SM_BUF;
    float* sx = sm + SM_SX;
    float2* woP = reinterpret_cast<float2*>(sm + SM_WOP);
    float* yx = sm + SM_YX;
    float* xch = buf;

    const int tid = threadIdx.x;
    const int mg = blockIdx.x & 31;
    const int bg = blockIdx.x >> 5;
    const int hid0 = mg * 16;
    const int b0 = bg * 64;
    const int lane = tid & 31, w = tid >> 5;
    const int ks = w >> 2, nq = w & 3;      // 4 K-slices x 4 n-quarters
    const int qr = lane >> 2, qc = lane & 3;
    const int n0 = nq * 16;
    const int orow0 = mg * 2;
    const int o0 = mg & 3;                  // rotated first slab
    const int wb_w = nq >> 1, hi_w = nq & 1;
    const int wXbase = (ks * 2 + wb_w) * 2048 + qr * 32;
    const int wbank0 = 4 * qr + qc + 16 * hi_w;

    const uint32_t smem_b = (uint32_t)__cvta_generic_to_shared(sm);
    const uint32_t buf_b = smem_b + SM_BUF * 4u;

    // pack gate weights into A-fragment layout (validated R1/R3/R5-R15)
    for (int idx = tid; idx < 72 * 96; idx += NTHR) {
        int kstep = idx / 96, r = idx % 96;
        int g = r >> 5, ln = r & 31;
        int lqr = ln >> 2, lqc = ln & 3;
        int row0 = g * HH + hid0 + lqr;
        int c0 = kstep * 8 + lqc, c1 = c0 + 4;
        float4 v;
        v.x = tf32r(c0 < HH ? w_hh[(size_t)row0 * HH + c0] : w_ih[(size_t)row0 * OO + c0 - HH]);
        v.y = tf32r(c0 < HH ? w_hh[(size_t)(row0 + 8) * HH + c0] : w_ih[(size_t)(row0 + 8) * OO + c0 - HH]);
        v.z = tf32r(c1 < HH ? w_hh[(size_t)row0 * HH + c1] : w_ih[(size_t)row0 * OO + c1 - HH]);
        v.w = tf32r(c1 < HH ? w_hh[(size_t)(row0 + 8) * HH + c1] : w_ih[(size_t)(row0 + 8) * OO + c1 - HH]);
        Wp4[idx] = v;
    }
    // pack y A-fragments: rows {w_out[orow0], w_out[orow0+1], 0...}, h-ksteps only
    for (int idx = tid; idx < 72 * 32; idx += NTHR) {
        int kstep = idx >> 5, ln = idx & 31;
        int lqr = ln >> 2, lqc = ln & 3;
        float2 v = make_float2(0.f, 0.f);
        if (kstep < 64 && lqr < 2) {
            int c0 = kstep * 8 + lqc;
            v.x = tf32r(w_out[(size_t)(orow0 + lqr) * HH + c0]);
            v.y = tf32r(w_out[(size_t)(orow0 + lqr) * HH + c0 + 4]);
        }
        woP[idx] = v;
    }

    const int krb = tid >> 6, bcol = tid & 63;
    float brv[2], bzv[2], binv[2], bhnv[2];
    #pragma unroll
    for (int r2 = 0; r2 < 2; ++r2) {
        int u = hid0 + krb + 8 * r2;
        brv[r2] = b_ih[u] + b_hh[u];
        bzv[r2] = b_ih[HH + u] + b_hh[HH + u];
        binv[r2] = b_ih[2 * HH + u];
        bhnv[r2] = b_hh[2 * HH + u];
    }
    const int hir = (bcol >> 4) & 1, wbr = bcol >> 5, jr = (bcol >> 3) & 1;
    const int qcr = (bcol & 7) >> 1, er = bcol & 1;
    const int rbank = (4 * krb + qcr + 8 * jr + 4 * er + 16 * hir) & 31;
    const int rbase = wbr * 2048 + krb * 32 + rbank;
    const float yb = (tid < 128) ? b_out[orow0 + (tid >> 6)] : 0.f;
    const int ynq = bcol >> 4, ylo = bcol & 15;

    // h_prev carried raw fp32 in registers (full-precision z*h path)
    float hprev[2];
    #pragma unroll
    for (int r2 = 0; r2 < 2; ++r2)
        hprev[r2] = code_vec[(size_t)(b0 + bcol) * HH + hid0 + krb + 8 * r2];

    // stage x[0] into sx; prefetch x[1] into registers
    float4 xr[2];
    #pragma unroll
    for (int j = 0; j < 2; ++j) {
        int idx = j * NTHR + tid;
        int row = idx >> 4, c4 = (idx & 15) << 2;
        *reinterpret_cast<float4*>(&sx[row * 72 + c4]) =
            *reinterpret_cast<const float4*>(g_xT + (size_t)row * BB + b0 + c4);
        xr[j] = *reinterpret_cast<const float4*>(g_xT + (size_t)OO * BB + (size_t)row * BB + b0 + c4);
    }
    __syncthreads();   // Wp/woP/sx[0] published

    for (int t = 0; t < TT; ++t) {
        const float* hsrc = g_hbuf[t & 1];

        float acc[3][2][4] = {}, accX[2][4] = {}, accY[2][4] = {};

        // slab0 cp.async issued FIRST (no sync before x-MMA; sx published by S4/pre-loop)
        {
            const float* src = hsrc + (size_t)(128 * o0) * BB + b0;
            #pragma unroll
            for (int j = 0; j < 4; ++j) {
                int idx = j * NTHR + tid;
                int row = idx >> 4, c4 = (idx & 15) << 2;
                cpa16(buf_b + (uint32_t)((row * 72 + c4) * 4), src + (size_t)row * BB + c4);
            }
        }
        asm volatile("cp.async.commit_group;\n");

        // x-path compute (covers slab0's L2 latency)
        #pragma unroll
        for (int c2 = 0; c2 < 2; ++c2) {
            const int gk = 64 + ks * 2 + c2;
            const int kk = (ks * 2 + c2) * 8;
            float bf0[2], bf1[2];
            #pragma unroll
            for (int j = 0; j < 2; ++j) {
                bf0[j] = sx[(kk + qc) * 72 + n0 + j * 8 + qr];
                bf1[j] = sx[(kk + 4 + qc) * 72 + n0 + j * 8 + qr];
            }
            float4 a0 = Wp4[(gk * 3 + 0) * 32 + lane];
            float4 a1 = Wp4[(gk * 3 + 1) * 32 + lane];
            float4 a2 = Wp4[(gk * 3 + 2) * 32 + lane];
            #pragma unroll
            for (int j = 0; j < 2; ++j) {
                mma8(acc[0][j], a0, bf0[j], bf1[j]);
                mma8(acc[1][j], a1, bf0[j], bf1[j]);
                mma8(accX[j], a2, bf0[j], bf1[j]);
            }
        }

        #pragma unroll
        for (int i = 0; i < 4; ++i) {
            asm volatile("cp.async.wait_group 0;\n");
            __syncthreads();
            if (i < 3) {
                const int pn = (o0 + i + 1) & 3;
                const float* src = hsrc + (size_t)(128 * pn) * BB + b0;
                uint32_t dstb = buf_b + (uint32_t)(((i + 1) & 1) * 9216 * 4);
                #pragma unroll
                for (int j = 0; j < 4; ++j) {
                    int idx = j * NTHR + tid;
                    int row = idx >> 4, c4 = (idx & 15) << 2;
                    cpa16(dstb + (uint32_t)((row * 72 + c4) * 4), src + (size_t)row * BB + c4);
                }
                asm volatile("cp.async.commit_group;\n");
            }
            const int p = (o0 + i) & 3;
            const float* bs = buf + (i & 1) * 9216;
            #pragma unroll
            for (int c = 0; c < 4; ++c) {
                const int gk = p * 16 + ks * 4 + c;
                const int kk = (ks * 4 + c) * 8;
                float bf0[2], bf1[2];
                #pragma unroll
                for (int j = 0; j < 2; ++j) {
                    bf0[j] = bs[(kk + qc) * 72 + n0 + j * 8 + qr];      // pre-rounded
                    bf1[j] = bs[(kk + 4 + qc) * 72 + n0 + j * 8 + qr];
                }
                #pragma unroll
                for (int g = 0; g < 3; ++g) {
                    float4 a4 = Wp4[(gk * 3 + g) * 32 + lane];
                    mma8(acc[g][0], a4, bf0[0], bf1[0]);
                    mma8(acc[g][1], a4, bf0[1], bf1[1]);
                }
                float2 ay2 = woP[gk * 32 + lane];
                float4 ay = make_float4(ay2.x, 0.f, ay2.y, 0.f);
                mma8(accY[0], ay, bf0[0], bf1[0]);
                mma8(accY[1], ay, bf0[1], bf1[1]);
            }
        }

        __syncthreads();  // S1: done reading buf/sx; overlay exchange
        #pragma unroll
        for (int g = 0; g < 4; ++g)
            #pragma unroll
            for (int rh = 0; rh < 2; ++rh)
                #pragma unroll
                for (int j = 0; j < 2; ++j)
                    #pragma unroll
                    for (int el = 0; el < 2; ++el) {
                        float v = (g < 3) ? acc[g][j][rh * 2 + el] : accX[j][rh * 2 + el];
                        xch[wXbase + g * 512 + rh * 256 + ((wbank0 + 8 * j + 4 * el) & 31)] = v;
                    }
        if (qr < 2) {
            #pragma unroll
            for (int j = 0; j < 2; ++j) {
                yx[(w * 2 + qr) * 16 + j * 8 + qc * 2] = accY[j][0];
                yx[(w * 2 + qr) * 16 + j * 8 + qc * 2 + 1] = accY[j][1];
            }
        }
        __syncthreads();  // S2

        // GRU update + h store (fast-math epilogue)
        float* hdst = g_hbuf[(t + 1) & 1];
        #pragma unroll
        for (int r2 = 0; r2 < 2; ++r2) {
            float q0 = 0.f, q1 = 0.f, q2s = 0.f, q3 = 0.f;
            #pragma unroll
            for (int ksx = 0; ksx < 4; ++ksx) {
                const float* sl = xch + rbase + ksx * 4096 + r2 * 256;
                q0 += sl[0]; q1 += sl[512]; q2s += sl[1024]; q3 += sl[1536];
            }
            float r = fsigmoid(q0 + brv[r2]);
            float z = fsigmoid(q1 + bzv[r2]);
            float n = ftanh(q3 + binv[r2] + r * (q2s + bhnv[r2]));
            float hv = (1.f - z) * n + z * hprev[r2];
            hprev[r2] = hv;
            hdst[(size_t)(hid0 + krb + 8 * r2) * BB + b0 + bcol] = tf32r(hv);
            if (t == TT - 1)
                out[(size_t)TT * BB * OO + (size_t)(b0 + bcol) * HH + hid0 + krb + 8 * r2] = hv;
        }
        __syncthreads();   // S3: all h stores done

        // early release (R12 barrier); overlap poll with y stores + x staging
        if (tid == 0)
            asm volatile("red.release.gpu.add.u32 [%0], %1;"
                         :: "l"(&g_cnt4[bg]), "r"(1u) : "memory");
        if (t > 0 && tid < 128) {
            int o2 = tid >> 6, b = tid & 63;
            float y = yb;
            #pragma unroll
            for (int ksx = 0; ksx < 4; ++ksx)
                y += yx[((ksx * 4 + ynq) * 2 + o2) * 16 + ylo];
            out[((size_t)(t - 1) * BB + b0 + b) * OO + orow0 + o2] = y;
        }
        // stage x[t+1] into sx NOW (published by S4); prefetch x[t+2]
        if (t + 1 < TT) {
            #pragma unroll
            for (int j = 0; j < 2; ++j) {
                int idx = j * NTHR + tid;
                int row = idx >> 4, c4 = (idx & 15) << 2;
                *reinterpret_cast<float4*>(&sx[row * 72 + c4]) = xr[j];
            }
            if (t + 2 < TT) {
                const float* xn = g_xT + (size_t)(t + 2) * OO * BB;
                #pragma unroll
                for (int j = 0; j < 2; ++j) {
                    int idx = j * NTHR + tid;
                    int row = idx >> 4, c4 = (idx & 15) << 2;
                    xr[j] = *reinterpret_cast<const float4*>(xn + (size_t)row * BB + b0 + c4);
                }
            }
        }
        if (tid == 0) {
            unsigned tgt = 32u * (unsigned)(t + 1), v;
            do {
                asm volatile("ld.acquire.gpu.u32 %0, [%1];" : "=r"(v) : "l"(&g_cnt4[bg]) : "memory");
            } while (v < tgt);
        }
        __syncthreads();  // S4: h[t+1] + sx(x[t+1]) published
    }

    // final y[1023] from h[1024]
    {
        const float* hsrc = g_hbuf[TT & 1];
        int o2 = (tid >> 6) & 1, q = tid >> 7;
        const int kbeg = q * 128;
        float yp = 0.f;
        for (int k = kbeg; k < kbeg + 128; ++k)
            yp = fmaf(hsrc[(size_t)k * BB + b0 + bcol], w_out[(size_t)(orow0 + o2) * HH + k], yp);
        __syncthreads();
        yx[(q * 2 + o2) * 64 + bcol] = yp;
        __syncthreads();
        if (tid < 128) {
            int oo2 = tid >> 6, b = tid & 63;
            float y = yx[oo2 * 64 + b] + yx[(2 + oo2) * 64 + b] +
                      yx[(4 + oo2) * 64 + b] + yx[(6 + oo2) * 64 + b] + yb;
            out[((size_t)(TT - 1) * BB + b0 + b) * OO + orow0 + oo2] = y;
        }
    }
}

extern "C" void kernel_launch(void* const* d_in, const int* in_sizes, int n_in,
                              void* d_out, int out_size) {
    const float* code_vec = (const float*)d_in[0];
    const float* target   = (const float*)d_in[1];
    const float* w_ih     = (const float*)d_in[2];
    const float* w_hh     = (const float*)d_in[3];
    const float* b_ih     = (const float*)d_in[4];
    const float* b_hh     = (const float*)d_in[5];
    const float* w_out    = (const float*)d_in[6];
    const float* b_out    = (const float*)d_in[7];
    float* out = (float*)d_out;

    const size_t smem_step = SM_TOTF * sizeof(float);   // 223232 B
    cudaFuncSetAttribute(gru_persistent, cudaFuncAttributeMaxDynamicSharedMemorySize, (int)smem_step);

    prep_h0<<<(HH * BB + 255) / 256, 256>>>(code_vec);       // idx 0
    prep_x<<<TT, 256>>>(target);                             // idx 1
    dummy_k<<<1, 32>>>(0);                                   // idx 2
    gru_persistent<<<NBLK, NTHR, smem_step>>>(out, code_vec, w_ih, w_hh, b_ih, b_hh, w_out, b_out);  // idx 3 <- ncu
}